// round 8
// baseline (speedup 1.0000x reference)
#include <cuda_runtime.h>
#include <cuda_bf16.h>

// class_logits [64,300,92] f32, pred_boxes [64,300,4] f32,
// tgt_labels [2048] i32, tgt_boxes [2048,4] f32  ->  out [64,300,2048] f32
#define BQ      19200
#define CC      92
#define TT      2048
#define ROWS    5       // rows per block: grid 7680 = 12.97 waves @ occ4 (99.8% util)
#define NTHR    256
#define TPT     4
#define TBLK    (NTHR * TPT)     // 1024
#define GRIDX   (BQ / ROWS)      // 3840
#define GRIDY   (TT / TBLK)      // 2
#define PT      8                // transposed prob row stride (floats); 32B, 16B-aligned

__device__ __forceinline__ float frcp(float x) {
    float y; asm("rcp.approx.f32 %0, %1;" : "=f"(y) : "f"(x)); return y;
}

__global__ __launch_bounds__(NTHR, 4)
void matcher_kernel(const float* __restrict__ logits,
                    const float* __restrict__ pboxes,
                    const int*   __restrict__ labels,
                    const float* __restrict__ tboxes,
                    float*       __restrict__ out)
{
    __shared__ float  s_probT[CC][PT];   // [class][row], holds (2 - prob)
    __shared__ float4 s_cw[ROWS];        // pcx, pcy, pw/2, ph/2
    __shared__ float  s_pa[ROWS];        // pw*ph

    const int tid  = threadIdx.x;
    const int warp = tid >> 5;           // warps 0..4 -> softmax rows
    const int lane = tid & 31;
    const int row0 = blockIdx.x * ROWS;

    // ---- Phase 1: per-row softmax (warp w -> row w, w<ROWS); transposed (2-prob) ----
    if (warp < ROWS) {
        const int rr = row0 + warp;
        const float* lrow = logits + (size_t)rr * CC;
        float l0 = lrow[lane];
        float l1 = lrow[lane + 32];
        float l2 = (lane + 64 < CC) ? lrow[lane + 64] : -1e30f;
        float m = fmaxf(l0, fmaxf(l1, l2));
        #pragma unroll
        for (int o = 16; o; o >>= 1) m = fmaxf(m, __shfl_xor_sync(0xffffffffu, m, o));
        float e0 = __expf(l0 - m);
        float e1 = __expf(l1 - m);
        float e2 = (lane + 64 < CC) ? __expf(l2 - m) : 0.0f;
        float s = e0 + e1 + e2;
        #pragma unroll
        for (int o = 16; o; o >>= 1) s += __shfl_xor_sync(0xffffffffu, s, o);
        float rinv = frcp(s);
        s_probT[lane][warp]      = fmaf(-e0, rinv, 2.0f);
        s_probT[lane + 32][warp] = fmaf(-e1, rinv, 2.0f);
        if (lane + 64 < CC) s_probT[lane + 64][warp] = fmaf(-e2, rinv, 2.0f);

        if (lane == 0) {
            float4 pb = *(const float4*)(pboxes + (size_t)rr * 4);
            s_cw[warp] = make_float4(pb.x, pb.y, 0.5f * pb.z, 0.5f * pb.w);
            s_pa[warp] = pb.z * pb.w;
        }
    }

    // ---- Phase 1b: this thread's 4 targets -> registers (5 floats each) ----
    const int tbase = blockIdx.y * TBLK + tid * TPT;
    float tcx[TPT], tcy[TPT], tw2[TPT], th2[TPT], ta[TPT];
    int lcls[TPT];
    {
        int4 lv = *(const int4*)(labels + tbase);
        lcls[0] = lv.x; lcls[1] = lv.y; lcls[2] = lv.z; lcls[3] = lv.w;
    }
    #pragma unroll
    for (int j = 0; j < TPT; j++) {
        float4 tb = *(const float4*)(tboxes + (size_t)(tbase + j) * 4);
        tcx[j] = tb.x; tcy[j] = tb.y;
        tw2[j] = 0.5f * tb.z;
        th2[j] = 0.5f * tb.w;
        ta[j]  = tb.z * tb.w;
    }
    __syncthreads();

    // Prefetch (2 - prob) for all ROWS rows per target: LDS.128 (rows 0-3) + scalar (row 4)
    float4 pra[TPT];
    float  prs[TPT];
    #pragma unroll
    for (int j = 0; j < TPT; j++) {
        pra[j] = *(const float4*)&s_probT[lcls[j]][0];
        prs[j] = s_probT[lcls[j]][4];
    }

    // ---- Phase 2: ROWS x 4 targets per thread ----
    // u = c_p - c_t, v = w2_p - w2_t, h = w2_p + w2_t, m = max(|u|,|v|):
    //   intersect = h - m (clamped), enclose = h + m, |dc| = |u|, |dw| = 2|v|
    // cost = 5(|ux|+|uy|) + 10(|vx|+|vy|) + (2-prob) - 2*inter/uni - 2*uni/ea
    float* const obase = out + (size_t)row0 * TT + tbase;

#define BODY(r, PRSEL)                                                         \
    {                                                                          \
        const float4 cw = s_cw[r];                                             \
        const float  pa = s_pa[r];                                             \
        float res[TPT];                                                        \
        _Pragma("unroll")                                                      \
        for (int j = 0; j < TPT; j++) {                                        \
            float ux = cw.x - tcx[j];                                          \
            float uy = cw.y - tcy[j];                                          \
            float vx = cw.z - tw2[j];                                          \
            float vy = cw.w - th2[j];                                          \
            float mx = fmaxf(fabsf(ux), fabsf(vx));                            \
            float my = fmaxf(fabsf(uy), fabsf(vy));                            \
            float hx = cw.z + tw2[j];                                          \
            float hy = cw.w + th2[j];                                          \
            float iw = fmaxf(hx - mx, 0.0f);                                   \
            float ih = fmaxf(hy - my, 0.0f);                                   \
            float ew = hx + mx;                                                \
            float eh = hy + my;                                                \
            float inter = iw * ih;                                             \
            float ea    = ew * eh;                                             \
            float uni   = (pa + ta[j]) - inter;                                \
            float t1    = inter * frcp(uni);                                   \
            float t2    = uni   * frcp(ea);                                    \
            float s1 = fabsf(ux) + fabsf(uy);                                  \
            float s2 = fabsf(vx) + fabsf(vy);                                  \
            float pr = PRSEL;                                                  \
            res[j] = fmaf(5.0f, s1, fmaf(10.0f, s2,                            \
                     fmaf(-2.0f, t1, fmaf(-2.0f, t2, pr))));                   \
        }                                                                      \
        *(float4*)(obase + (size_t)(r) * TT) =                                 \
            make_float4(res[0], res[1], res[2], res[3]);                       \
    }

    BODY(0, pra[j].x)
    BODY(1, pra[j].y)
    BODY(2, pra[j].z)
    BODY(3, pra[j].w)
    BODY(4, prs[j])
#undef BODY
}

extern "C" void kernel_launch(void* const* d_in, const int* in_sizes, int n_in,
                              void* d_out, int out_size) {
    const float* logits = (const float*)d_in[0];
    const float* pboxes = (const float*)d_in[1];
    const int*   labels = (const int*)  d_in[2];
    const float* tboxes = (const float*)d_in[3];
    float* out = (float*)d_out;
    matcher_kernel<<<dim3(GRIDX, GRIDY), NTHR>>>(logits, pboxes, labels, tboxes, out);
}